// round 15
// baseline (speedup 1.0000x reference)
#include <cuda_runtime.h>
#include <cuda_bf16.h>
#include <cstdint>

#define B_ 256
#define N_ 5
#define D_ 2048
#define C_ 1000
#define H_ 1024
#define PROTO_M 0.999f
#define EPS_ 1e-12f
#define GRID_G 296   // 148 SMs x 2 CTA slots
#define LUT_W 24
#define MAX_T 160

// ==================== scratch (static device globals) ====================
__device__ __nv_bfloat16 g_ax_hi[B_ * N_ * D_], g_ax_lo[B_ * N_ * D_];
__device__ __nv_bfloat16 g_ah_hi[B_ * N_ * H_], g_ah_lo[B_ * N_ * H_];
__device__ __nv_bfloat16 g_nd_hi[B_ * N_ * D_], g_nd_lo[B_ * N_ * D_];
__device__ __nv_bfloat16 g_g_hi[B_ * D_], g_g_lo[B_ * D_];
__device__ float g_part[2 * GRID_G * 128 * 128];   // stream-K partials: 2 segs/unit
__device__ int g_fin[4 * MAX_T];                   // finisher counters per gemm id

__device__ float g_scale[C_];
__device__ int   g_off[C_ + 1];
__device__ int   g_idx[B_];
__device__ float g_w[B_];

// ==================== helpers ====================
__device__ __forceinline__ void split_bf16(float v, __nv_bfloat16& hi, __nv_bfloat16& lo) {
    hi = __float2bfloat16_rn(v);
    lo = __float2bfloat16_rn(v - __bfloat162float(hi));
}
__device__ __forceinline__ uint32_t smem_u32(const void* p) {
    uint32_t a;
    asm("{ .reg .u64 t; cvta.to.shared.u64 t, %1; cvt.u32.u64 %0, t; }" : "=r"(a) : "l"(p));
    return a;
}
__device__ __forceinline__ void cp_async16(uint32_t dst, const void* src) {
    asm volatile("cp.async.cg.shared.global [%0], [%1], 16;" :: "r"(dst), "l"(src));
}
__device__ __forceinline__ void cp_commit() { asm volatile("cp.async.commit_group;" ::: "memory"); }
__device__ __forceinline__ void cp_wait0() { asm volatile("cp.async.wait_group 0;" ::: "memory"); }

__device__ __forceinline__ void ldsm_x4(uint32_t* r, uint32_t addr) {
    asm volatile("ldmatrix.sync.aligned.m8n8.x4.shared.b16 {%0,%1,%2,%3}, [%4];"
        : "=r"(r[0]), "=r"(r[1]), "=r"(r[2]), "=r"(r[3]) : "r"(addr));
}
__device__ __forceinline__ void ldsm_x4_t(uint32_t* r, uint32_t addr) {
    asm volatile("ldmatrix.sync.aligned.m8n8.x4.trans.shared.b16 {%0,%1,%2,%3}, [%4];"
        : "=r"(r[0]), "=r"(r[1]), "=r"(r[2]), "=r"(r[3]) : "r"(addr));
}
__device__ __forceinline__ void mma16816(float* c, const uint32_t* a, uint32_t b0, uint32_t b1) {
    asm volatile(
        "mma.sync.aligned.m16n8k16.row.col.f32.bf16.bf16.f32 "
        "{%0,%1,%2,%3}, {%4,%5,%6,%7}, {%8,%9}, {%0,%1,%2,%3};"
        : "+f"(c[0]), "+f"(c[1]), "+f"(c[2]), "+f"(c[3])
        : "r"(a[0]), "r"(a[1]), "r"(a[2]), "r"(a[3]), "r"(b0), "r"(b1));
}

// units/segments covering tile t (ascending unit order -> deterministic sums)
__device__ __forceinline__ int tile_units(int t, int Ct, int TC, int* list) {
    int gb = t * Ct, ge = gb + Ct;
    int u = (int)(((long)(gb + 1) * GRID_G - 1) / TC);
    int cnt = 0;
    for (;;) {
        int u0 = (int)((long)u * TC / GRID_G);
        int seg = t - u0 / Ct;
        if (list) list[cnt] = 2 * u + seg;
        cnt++;
        int u1 = (int)((long)(u + 1) * TC / GRID_G);
        if (u1 >= ge) break;
        u++;
    }
    return cnt;
}

// ==================== adj-mix + hi/lo convert (float4) + counter reset ====================
__global__ void adjmix_convert_kernel(const float* __restrict__ in,
                                      const float* __restrict__ adj,
                                      __nv_bfloat16* __restrict__ hi,
                                      __nv_bfloat16* __restrict__ lo, int F) {
    if (blockIdx.x == 0)
        for (int i = threadIdx.x; i < 4 * MAX_T; i += blockDim.x) g_fin[i] = 0;

    int t = blockIdx.x * blockDim.x + threadIdx.x;
    int F4 = F >> 2;
    if (t >= B_ * F4) return;
    int b = t / F4, f = (t % F4) * 4;
    float xv[N_][4];
#pragma unroll
    for (int m = 0; m < N_; m++) {
        float4 v = *reinterpret_cast<const float4*>(in + ((size_t)b * N_ + m) * F + f);
        xv[m][0] = v.x; xv[m][1] = v.y; xv[m][2] = v.z; xv[m][3] = v.w;
    }
#pragma unroll
    for (int n = 0; n < N_; n++) {
        float s[4] = {0.f, 0.f, 0.f, 0.f};
#pragma unroll
        for (int m = 0; m < N_; m++) {
            float a = adj[n * N_ + m];
#pragma unroll
            for (int k = 0; k < 4; k++) s[k] += a * xv[m][k];
        }
        __nv_bfloat16 h0, l0, h1, l1;
        split_bf16(s[0], h0, l0); split_bf16(s[1], h1, l1);
        __nv_bfloat162 p0; p0.x = h0; p0.y = h1;
        __nv_bfloat162 q0; q0.x = l0; q0.y = l1;
        split_bf16(s[2], h0, l0); split_bf16(s[3], h1, l1);
        __nv_bfloat162 p1; p1.x = h0; p1.y = h1;
        __nv_bfloat162 q1; q1.x = l0; q1.y = l1;
        *reinterpret_cast<uint2*>(hi + ((size_t)b * N_ + n) * F + f) =
            make_uint2(*reinterpret_cast<uint32_t*>(&p0), *reinterpret_cast<uint32_t*>(&p1));
        *reinterpret_cast<uint2*>(lo + ((size_t)b * N_ + n) * F + f) =
            make_uint2(*reinterpret_cast<uint32_t*>(&q0), *reinterpret_cast<uint32_t*>(&q1));
    }
}

// ==================== HMMA GEMM: stream-K + fused finisher epilogue ====================
// EPI: 0 = partials only; 1 = convert hi/lo; 2 = bias + convert hi/lo; 3 = bias + f32 out (strip pad)
#define SMEM_TOTAL_GEMM 75776
template <int EPI>
__global__ void __launch_bounds__(256, 2)
gemm_sk(const __nv_bfloat16* __restrict__ A_hi, const __nv_bfloat16* __restrict__ A_lo,
        const float* __restrict__ W, float* __restrict__ P,
        int Nw, int K, int NTx, int T, int Ct,
        __nv_bfloat16* __restrict__ Ohi, __nv_bfloat16* __restrict__ Olo,
        const float* __restrict__ bias, float* __restrict__ OutF, int gid) {
    extern __shared__ __align__(16) uint8_t smem[];
    const uint32_t base = smem_u32(smem);
    const uint32_t oAhi = 0, oAlo = 20480, oBhi = 40960, oBlo = 58368;
    const uint32_t strA = 10240, strB = 8704;

    const int G = gridDim.x;
    const int TC = T * Ct;
    const int u = blockIdx.x;
    const int g0 = (int)((long)u * TC / G);
    const int g1 = (int)((long)(u + 1) * TC / G);
    const int NC = g1 - g0;

    const int tid = threadIdx.x;
    const int lane = tid & 31, warp = tid >> 5;
    const int wr = warp & 3, wc = warp >> 2;

    const int ar0 = tid >> 2, aq0 = tid & 3;
    const int ar1 = (tid + 256) >> 2, aq1 = (tid + 256) & 3;
    int wk[4], wq[4];
#pragma unroll
    for (int i = 0; i < 4; i++) {
        int idx = tid + i * 256;
        wk[i] = idx >> 5; wq[i] = idx & 31;
    }

    const int selRow = (lane & 7) + ((lane >> 3) & 1) * 8;
    const int selHi = (lane >> 4) & 1;
    const uint32_t aOff = (uint32_t)((wr * 32 + selRow) * 80 + selHi * 16);
    const uint32_t bOff = (uint32_t)(selRow * 272 + wc * 128 + selHi * 16);

    float acc[2][8][4] = {};
    float4 wreg[4];

    auto stageA = [&](int g, int buf) {
        int t = g / Ct, c = g - t * Ct;
        int row0 = (t / NTx) * 128;
        int kk = c * 32;
        uint32_t da = base + oAhi + buf * strA;
        uint32_t dl = base + oAlo + buf * strA;
        cp_async16(da + ar0 * 80 + aq0 * 16, A_hi + (size_t)(row0 + ar0) * K + kk + aq0 * 8);
        cp_async16(da + ar1 * 80 + aq1 * 16, A_hi + (size_t)(row0 + ar1) * K + kk + aq1 * 8);
        cp_async16(dl + ar0 * 80 + aq0 * 16, A_lo + (size_t)(row0 + ar0) * K + kk + aq0 * 8);
        cp_async16(dl + ar1 * 80 + aq1 * 16, A_lo + (size_t)(row0 + ar1) * K + kk + aq1 * 8);
    };

    auto ldgW = [&](int g) {
        int t = g / Ct, c = g - t * Ct;
        int col0 = (t % NTx) * 128;
        int kk = c * 32;
#pragma unroll
        for (int i = 0; i < 4; i++) {
            int col = col0 + wq[i] * 4;
            const float* src = W + (size_t)(kk + wk[i]) * Nw + col;
            if (col + 3 < Nw) {
                wreg[i] = *reinterpret_cast<const float4*>(src);
            } else {
                wreg[i].x = (col + 0 < Nw) ? src[0] : 0.f;
                wreg[i].y = (col + 1 < Nw) ? src[1] : 0.f;
                wreg[i].z = (col + 2 < Nw) ? src[2] : 0.f;
                wreg[i].w = (col + 3 < Nw) ? src[3] : 0.f;
            }
        }
    };

    auto convertW = [&](int buf) {
#pragma unroll
        for (int i = 0; i < 4; i++) {
            float4 v = wreg[i];
            __nv_bfloat16 h0, l0, h1, l1, h2, l2, h3, l3;
            split_bf16(v.x, h0, l0); split_bf16(v.y, h1, l1);
            split_bf16(v.z, h2, l2); split_bf16(v.w, h3, l3);
            __nv_bfloat162 hA, hB, lA, lB;
            hA.x = h0; hA.y = h1; hB.x = h2; hB.y = h3;
            lA.x = l0; lA.y = l1; lB.x = l2; lB.y = l3;
            uint2 hp = make_uint2(*reinterpret_cast<uint32_t*>(&hA),
                                  *reinterpret_cast<uint32_t*>(&hB));
            uint2 lp = make_uint2(*reinterpret_cast<uint32_t*>(&lA),
                                  *reinterpret_cast<uint32_t*>(&lB));
            uint32_t off = (uint32_t)(wk[i] * 272 + wq[i] * 8);
            *reinterpret_cast<uint2*>(smem + (oBhi + buf * strB) + off) = hp;
            *reinterpret_cast<uint2*>(smem + (oBlo + buf * strB) + off) = lp;
        }
    };

    const int g = lane >> 2, tg = lane & 3;
    int seg = 0;
    auto flush = [&]() {
        float* up = P + (size_t)(2 * u + seg) * 16384;
#pragma unroll
        for (int mi = 0; mi < 2; mi++)
#pragma unroll
            for (int half = 0; half < 2; half++) {
                int lr = wr * 32 + mi * 16 + g + half * 8;
                float* rowp = up + lr * 128 + wc * 64;
#pragma unroll
                for (int ni = 0; ni < 8; ni++)
                    *reinterpret_cast<float2*>(rowp + ni * 8 + tg * 2) =
                        make_float2(acc[mi][ni][half * 2], acc[mi][ni][half * 2 + 1]);
            }
        seg++;
#pragma unroll
        for (int mi = 0; mi < 2; mi++)
#pragma unroll
            for (int ni = 0; ni < 8; ni++)
#pragma unroll
                for (int k2 = 0; k2 < 4; k2++) acc[mi][ni][k2] = 0.f;
    };

    // prologue
    stageA(g0, 0);
    cp_commit();
    ldgW(g0);
    convertW(0);
    if (NC > 1) ldgW(g0 + 1);
    cp_wait0();
    __syncthreads();
    if (NC > 1) { stageA(g0 + 1, 1); cp_commit(); }

    for (int li = 0; li < NC; li++) {
        const int gc = g0 + li;
        const int buf = li & 1;
        const uint32_t ah = base + oAhi + buf * strA, al = base + oAlo + buf * strA;
        const uint32_t bh = base + oBhi + buf * strB, bl = base + oBlo + buf * strB;

#pragma unroll
        for (int ks = 0; ks < 2; ks++) {
            uint32_t faH[2][4], faL[2][4], fb[4][4];
            ldsm_x4(faH[0], ah + aOff + ks * 32);
            ldsm_x4(faH[1], ah + aOff + 1280 + ks * 32);
            ldsm_x4(faL[0], al + aOff + ks * 32);
            ldsm_x4(faL[1], al + aOff + 1280 + ks * 32);
#pragma unroll
            for (int p = 0; p < 4; p++) ldsm_x4_t(fb[p], bh + bOff + ks * 4352 + p * 32);
#pragma unroll
            for (int mi = 0; mi < 2; mi++)
#pragma unroll
                for (int p = 0; p < 4; p++) {
                    mma16816(acc[mi][2 * p], faH[mi], fb[p][0], fb[p][1]);
                    mma16816(acc[mi][2 * p + 1], faH[mi], fb[p][2], fb[p][3]);
                }
#pragma unroll
            for (int mi = 0; mi < 2; mi++)
#pragma unroll
                for (int p = 0; p < 4; p++) {
                    mma16816(acc[mi][2 * p], faL[mi], fb[p][0], fb[p][1]);
                    mma16816(acc[mi][2 * p + 1], faL[mi], fb[p][2], fb[p][3]);
                }
#pragma unroll
            for (int p = 0; p < 4; p++) ldsm_x4_t(fb[p], bl + bOff + ks * 4352 + p * 32);
#pragma unroll
            for (int mi = 0; mi < 2; mi++)
#pragma unroll
                for (int p = 0; p < 4; p++) {
                    mma16816(acc[mi][2 * p], faH[mi], fb[p][0], fb[p][1]);
                    mma16816(acc[mi][2 * p + 1], faH[mi], fb[p][2], fb[p][3]);
                }
        }

        if (gc + 1 == g1 || (gc + 1) % Ct == 0) flush();

        if (li + 1 < NC) convertW(buf ^ 1);
        cp_wait0();
        __syncthreads();
        if (li + 2 < NC) { ldgW(g0 + li + 2); stageA(g0 + li + 2, buf); cp_commit(); }
    }

    // ---- fused finisher epilogue ----
    if (EPI != 0) {
        __shared__ int s_rank[2];
        __shared__ int s_list[LUT_W];
        __shared__ int s_tot;
        const int t0 = g0 / Ct, t1 = (g1 - 1) / Ct;
        const int nseg = seg;   // 1 or 2
        __threadfence();
        if (tid == 0) {
            s_rank[0] = atomicAdd(&g_fin[gid * MAX_T + t0], 1);
            if (nseg > 1) s_rank[1] = atomicAdd(&g_fin[gid * MAX_T + t1], 1);
        }
        __syncthreads();
        for (int si = 0; si < nseg; si++) {
            int t = (si == 0) ? t0 : t1;
            __syncthreads();
            if (tid == 0) s_tot = tile_units(t, Ct, TC, s_list);
            __syncthreads();
            if (s_rank[si] != s_tot - 1) continue;   // uniform branch (smem)
            __threadfence();
            const int cnt = s_tot;
            const int row0t = (t / NTx) * 128, col0t = (t % NTx) * 128;
            const int Nout = NTx * 128;
            for (int p = tid; p < 4096; p += 256) {
                int lr = p >> 5, lc = (p & 31) * 4;
                float4 s = make_float4(0.f, 0.f, 0.f, 0.f);
                for (int j = 0; j < cnt; j++) {
                    float4 v = *reinterpret_cast<const float4*>(
                        P + (size_t)s_list[j] * 16384 + lr * 128 + lc);
                    s.x += v.x; s.y += v.y; s.z += v.z; s.w += v.w;
                }
                int row = row0t + lr, col = col0t + lc;
                if (EPI == 3) {
                    if (col < C_) OutF[(size_t)row * C_ + col] = s.x + bias[col];
                    if (col + 1 < C_) OutF[(size_t)row * C_ + col + 1] = s.y + bias[col + 1];
                    if (col + 2 < C_) OutF[(size_t)row * C_ + col + 2] = s.z + bias[col + 2];
                    if (col + 3 < C_) OutF[(size_t)row * C_ + col + 3] = s.w + bias[col + 3];
                } else {
                    if (EPI == 2) {
                        float4 bv = *reinterpret_cast<const float4*>(bias + col);
                        s.x += bv.x; s.y += bv.y; s.z += bv.z; s.w += bv.w;
                    }
                    __nv_bfloat16 h0, l0, h1, l1;
                    split_bf16(s.x, h0, l0); split_bf16(s.y, h1, l1);
                    __nv_bfloat162 p0; p0.x = h0; p0.y = h1;
                    __nv_bfloat162 q0; q0.x = l0; q0.y = l1;
                    split_bf16(s.z, h0, l0); split_bf16(s.w, h1, l1);
                    __nv_bfloat162 p1; p1.x = h0; p1.y = h1;
                    __nv_bfloat162 q1; q1.x = l0; q1.y = l1;
                    *reinterpret_cast<uint2*>(Ohi + (size_t)row * Nout + col) =
                        make_uint2(*reinterpret_cast<uint32_t*>(&p0),
                                   *reinterpret_cast<uint32_t*>(&p1));
                    *reinterpret_cast<uint2*>(Olo + (size_t)row * Nout + col) =
                        make_uint2(*reinterpret_cast<uint32_t*>(&q0),
                                   *reinterpret_cast<uint32_t*>(&q1));
                }
            }
        }
    }
}

// ==================== reduce1: relu + adj-mix + convert (smem LUT, float4) ====================
__device__ __forceinline__ void build_lut_smem(int* s_lut, int* s_cnt, int T, int Ct, int TC) {
    for (int t = threadIdx.x; t < T; t += blockDim.x)
        s_cnt[t] = tile_units(t, Ct, TC, s_lut + t * LUT_W);
    __syncthreads();
}
__device__ __forceinline__ float4 sum_tile4(const float* __restrict__ P, const int* s_lut,
                                            const int* s_cnt, int t, int lr, int lc) {
    int cnt = s_cnt[t];
    const int* lp = s_lut + t * LUT_W;
    float4 s = make_float4(0.f, 0.f, 0.f, 0.f);
    for (int j = 0; j < cnt; j++) {
        float4 v = *reinterpret_cast<const float4*>(P + (size_t)lp[j] * 16384 + lr * 128 + lc);
        s.x += v.x; s.y += v.y; s.z += v.z; s.w += v.w;
    }
    return s;
}

__global__ void reduce_relu_adjmix_convert_kernel(const float* __restrict__ P,
                                                  const float* __restrict__ adj,
                                                  __nv_bfloat16* __restrict__ hi,
                                                  __nv_bfloat16* __restrict__ lo,
                                                  int F, int NTx, int T, int Ct, int TC) {
    __shared__ int s_lut[MAX_T * LUT_W];
    __shared__ int s_cnt[MAX_T];
    build_lut_smem(s_lut, s_cnt, T, Ct, TC);

    int t = blockIdx.x * blockDim.x + threadIdx.x;
    int F4 = F >> 2;
    if (t >= B_ * F4) return;
    int b = t / F4, f = (t % F4) * 4;
    float hv[N_][4];
#pragma unroll
    for (int m = 0; m < N_; m++) {
        int row = b * N_ + m;
        int tile = (row >> 7) * NTx + (f >> 7);
        float4 v = sum_tile4(P, s_lut, s_cnt, tile, row & 127, f & 127);
        hv[m][0] = fmaxf(v.x, 0.f); hv[m][1] = fmaxf(v.y, 0.f);
        hv[m][2] = fmaxf(v.z, 0.f); hv[m][3] = fmaxf(v.w, 0.f);
    }
#pragma unroll
    for (int n = 0; n < N_; n++) {
        float s[4] = {0.f, 0.f, 0.f, 0.f};
#pragma unroll
        for (int m = 0; m < N_; m++) {
            float a = adj[n * N_ + m];
#pragma unroll
            for (int k = 0; k < 4; k++) s[k] += a * hv[m][k];
        }
        __nv_bfloat16 h0, l0, h1, l1;
        split_bf16(s[0], h0, l0); split_bf16(s[1], h1, l1);
        __nv_bfloat162 p0; p0.x = h0; p0.y = h1;
        __nv_bfloat162 q0; q0.x = l0; q0.y = l1;
        split_bf16(s[2], h0, l0); split_bf16(s[3], h1, l1);
        __nv_bfloat162 p1; p1.x = h0; p1.y = h1;
        __nv_bfloat162 q1; q1.x = l0; q1.y = l1;
        *reinterpret_cast<uint2*>(hi + ((size_t)b * N_ + n) * F + f) =
            make_uint2(*reinterpret_cast<uint32_t*>(&p0), *reinterpret_cast<uint32_t*>(&p1));
        *reinterpret_cast<uint2*>(lo + ((size_t)b * N_ + n) * F + f) =
            make_uint2(*reinterpret_cast<uint32_t*>(&q0), *reinterpret_cast<uint32_t*>(&q1));
    }
}

// ==================== prototype EMA (closed form), parallel metadata ====================
__global__ void class_meta_kernel(const int* __restrict__ target) {  // 1 block, 1024 thr
    __shared__ int cnt[1024];
    __shared__ int scan[1024];
    __shared__ int t_s[B_];
    __shared__ int rank_s[B_];
    int tid = threadIdx.x;
    cnt[tid] = 0;
    __syncthreads();
    if (tid < B_) t_s[tid] = target[tid];
    __syncthreads();
    if (tid < B_) {
        int c = t_s[tid], r = 0;
        for (int j = 0; j < tid; j++) r += (t_s[j] == c) ? 1 : 0;
        rank_s[tid] = r;
        atomicAdd(&cnt[c], 1);
    }
    __syncthreads();
    if (tid < C_) g_scale[tid] = powf(PROTO_M, (float)cnt[tid]);
    scan[tid] = cnt[tid];
    __syncthreads();
    for (int ofs = 1; ofs < 1024; ofs <<= 1) {
        int v = (tid >= ofs) ? scan[tid - ofs] : 0;
        __syncthreads();
        scan[tid] += v;
        __syncthreads();
    }
    if (tid < C_) g_off[tid] = scan[tid] - cnt[tid];
    if (tid == 0) g_off[C_] = B_;
    __syncthreads();
    if (tid < B_) {
        int c = t_s[tid];
        int p = (scan[c] - cnt[c]) + rank_s[tid];
        g_idx[p] = tid;
        g_w[p] = (1.0f - PROTO_M) * powf(PROTO_M, (float)(cnt[c] - 1 - rank_s[tid]));
    }
}

__global__ void proto_update_kernel(const float* __restrict__ x,
                                    const float* __restrict__ protos,
                                    float* __restrict__ out) {
    int t = blockIdx.x * blockDim.x + threadIdx.x;
    const int D4 = D_ / 4;
    if (t >= C_ * D4) return;
    int c = t / D4, d4 = t % D4;
    float s = g_scale[c];
    float4 v[N_];
#pragma unroll
    for (int n = 0; n < N_; n++) {
        float4 p = *reinterpret_cast<const float4*>(protos + ((size_t)c * N_ + n) * D_ + d4 * 4);
        v[n] = make_float4(p.x * s, p.y * s, p.z * s, p.w * s);
    }
    int e = g_off[c + 1];
    for (int j = g_off[c]; j < e; j++) {
        int i = g_idx[j];
        float w = g_w[j];
#pragma unroll
        for (int n = 0; n < N_; n++) {
            float4 xv = *reinterpret_cast<const float4*>(x + ((size_t)i * N_ + n) * D_ + d4 * 4);
            v[n].x += w * xv.x; v[n].y += w * xv.y;
            v[n].z += w * xv.z; v[n].w += w * xv.w;
        }
    }
    float4 nrm4 = make_float4(0.f, 0.f, 0.f, 0.f);
#pragma unroll
    for (int n = 0; n < N_; n++) {
        nrm4.x += v[n].x * v[n].x; nrm4.y += v[n].y * v[n].y;
        nrm4.z += v[n].z * v[n].z; nrm4.w += v[n].w * v[n].w;
    }
    float4 inv = make_float4(1.f / fmaxf(sqrtf(nrm4.x), EPS_), 1.f / fmaxf(sqrtf(nrm4.y), EPS_),
                             1.f / fmaxf(sqrtf(nrm4.z), EPS_), 1.f / fmaxf(sqrtf(nrm4.w), EPS_));
#pragma unroll
    for (int n = 0; n < N_; n++) {
        float4 o = make_float4(v[n].x * inv.x, v[n].y * inv.y, v[n].z * inv.z, v[n].w * inv.w);
        *reinterpret_cast<float4*>(out + ((size_t)c * N_ + n) * D_ + d4 * 4) = o;
    }
}

// ==================== launch ====================
extern "C" void kernel_launch(void* const* d_in, const int* in_sizes, int n_in,
                              void* d_out, int out_size) {
    const float* x    = (const float*)d_in[0];
    const int*   tgt  = (const int*)d_in[1];
    const float* prot = (const float*)d_in[2];
    const float* adj  = (const float*)d_in[3];
    const float* W1   = (const float*)d_in[4];
    const float* W2   = (const float*)d_in[5];
    const float* Wg   = (const float*)d_in[6];
    const float* bg   = (const float*)d_in[7];
    const float* Wc   = (const float*)d_in[8];
    const float* bc   = (const float*)d_in[9];

    float* pred_out  = (float*)d_out;
    float* proto_out = (float*)d_out + (size_t)B_ * C_;

    __nv_bfloat16 *ax_hi, *ax_lo, *ah_hi, *ah_lo, *nd_hi, *nd_lo, *gg_hi, *gg_lo;
    float* part;
    cudaGetSymbolAddress((void**)&ax_hi, g_ax_hi);   cudaGetSymbolAddress((void**)&ax_lo, g_ax_lo);
    cudaGetSymbolAddress((void**)&ah_hi, g_ah_hi);   cudaGetSymbolAddress((void**)&ah_lo, g_ah_lo);
    cudaGetSymbolAddress((void**)&nd_hi, g_nd_hi);   cudaGetSymbolAddress((void**)&nd_lo, g_nd_lo);
    cudaGetSymbolAddress((void**)&gg_hi, g_g_hi);    cudaGetSymbolAddress((void**)&gg_lo, g_g_lo);
    cudaGetSymbolAddress((void**)&part, g_part);

    cudaFuncSetAttribute(gemm_sk<0>, cudaFuncAttributeMaxDynamicSharedMemorySize, SMEM_TOTAL_GEMM);
    cudaFuncSetAttribute(gemm_sk<1>, cudaFuncAttributeMaxDynamicSharedMemorySize, SMEM_TOTAL_GEMM);
    cudaFuncSetAttribute(gemm_sk<2>, cudaFuncAttributeMaxDynamicSharedMemorySize, SMEM_TOTAL_GEMM);
    cudaFuncSetAttribute(gemm_sk<3>, cudaFuncAttributeMaxDynamicSharedMemorySize, SMEM_TOTAL_GEMM);

    // ax = adj @ x (+ hi/lo convert) + finisher-counter reset
    adjmix_convert_kernel<<<(B_ * (D_ / 4) + 255) / 256, 256>>>(x, adj, ax_hi, ax_lo, D_);

    // GEMM1: [1280,2048]@W1[2048,1024]. T=80 (10x8), Ct=64. EPI=0 + separate reduce.
    gemm_sk<0><<<GRID_G, 256, SMEM_TOTAL_GEMM>>>(
        ax_hi, ax_lo, W1, part, H_, D_, 8, 80, 64,
        nullptr, nullptr, nullptr, nullptr, 0);
    reduce_relu_adjmix_convert_kernel<<<(B_ * (H_ / 4) + 255) / 256, 256>>>(
        part, adj, ah_hi, ah_lo, H_, 8, 80, 64, 5120);

    // GEMM2: [1280,1024]@W2[1024,2048]. T=160 (10x16), Ct=32. EPI=1 -> nd hi/lo.
    gemm_sk<1><<<GRID_G, 256, SMEM_TOTAL_GEMM>>>(
        ah_hi, ah_lo, W2, part, D_, H_, 16, 160, 32,
        nd_hi, nd_lo, nullptr, nullptr, 1);

    // fc_g: [256,10240]@Wg[10240,2048]. T=32 (2x16), Ct=320. EPI=2 -> gg hi/lo (+bg).
    gemm_sk<2><<<GRID_G, 256, SMEM_TOTAL_GEMM>>>(
        nd_hi, nd_lo, Wg, part, D_, N_ * D_, 16, 32, 320,
        gg_hi, gg_lo, bg, nullptr, 2);

    // fc_cls: [256,2048]@Wc[2048,1000 pad 1024]. T=16 (2x8), Ct=64. EPI=3 -> pred (+bc).
    gemm_sk<3><<<GRID_G, 256, SMEM_TOTAL_GEMM>>>(
        gg_hi, gg_lo, Wc, part, C_, D_, 8, 16, 64,
        nullptr, nullptr, bc, pred_out, 3);

    // prototypes
    class_meta_kernel<<<1, 1024>>>(tgt);
    proto_update_kernel<<<(C_ * (D_ / 4) + 255) / 256, 256>>>(x, prot, proto_out);
}

// round 16
// speedup vs baseline: 1.2199x; 1.2199x over previous
#include <cuda_runtime.h>
#include <cuda_bf16.h>
#include <cstdint>

#define B_ 256
#define N_ 5
#define D_ 2048
#define C_ 1000
#define H_ 1024
#define PROTO_M 0.999f
#define EPS_ 1e-12f
#define GRID_G 296   // 148 SMs x 2 CTA slots
#define LUT_W 24
#define MAX_T 160

// ==================== scratch (static device globals) ====================
__device__ __nv_bfloat16 g_ax_hi[B_ * N_ * D_], g_ax_lo[B_ * N_ * D_];
__device__ __nv_bfloat16 g_ah_hi[B_ * N_ * H_], g_ah_lo[B_ * N_ * H_];
__device__ __nv_bfloat16 g_nd_hi[B_ * N_ * D_], g_nd_lo[B_ * N_ * D_];
__device__ __nv_bfloat16 g_g_hi[B_ * D_], g_g_lo[B_ * D_];
__device__ float g_part[2 * GRID_G * 128 * 128];   // stream-K partials: 2 segs/unit

__device__ float g_scale[C_];
__device__ int   g_off[C_ + 1];
__device__ int   g_idx[B_];
__device__ float g_w[B_];

// ==================== helpers ====================
__device__ __forceinline__ void split_bf16(float v, __nv_bfloat16& hi, __nv_bfloat16& lo) {
    hi = __float2bfloat16_rn(v);
    lo = __float2bfloat16_rn(v - __bfloat162float(hi));
}
__device__ __forceinline__ uint32_t smem_u32(const void* p) {
    uint32_t a;
    asm("{ .reg .u64 t; cvta.to.shared.u64 t, %1; cvt.u32.u64 %0, t; }" : "=r"(a) : "l"(p));
    return a;
}
__device__ __forceinline__ void cp_async16(uint32_t dst, const void* src) {
    asm volatile("cp.async.cg.shared.global [%0], [%1], 16;" :: "r"(dst), "l"(src));
}
__device__ __forceinline__ void cp_commit() { asm volatile("cp.async.commit_group;" ::: "memory"); }
__device__ __forceinline__ void cp_wait0() { asm volatile("cp.async.wait_group 0;" ::: "memory"); }

__device__ __forceinline__ void ldsm_x4(uint32_t* r, uint32_t addr) {
    asm volatile("ldmatrix.sync.aligned.m8n8.x4.shared.b16 {%0,%1,%2,%3}, [%4];"
        : "=r"(r[0]), "=r"(r[1]), "=r"(r[2]), "=r"(r[3]) : "r"(addr));
}
__device__ __forceinline__ void ldsm_x4_t(uint32_t* r, uint32_t addr) {
    asm volatile("ldmatrix.sync.aligned.m8n8.x4.trans.shared.b16 {%0,%1,%2,%3}, [%4];"
        : "=r"(r[0]), "=r"(r[1]), "=r"(r[2]), "=r"(r[3]) : "r"(addr));
}
__device__ __forceinline__ void mma16816(float* c, const uint32_t* a, uint32_t b0, uint32_t b1) {
    asm volatile(
        "mma.sync.aligned.m16n8k16.row.col.f32.bf16.bf16.f32 "
        "{%0,%1,%2,%3}, {%4,%5,%6,%7}, {%8,%9}, {%0,%1,%2,%3};"
        : "+f"(c[0]), "+f"(c[1]), "+f"(c[2]), "+f"(c[3])
        : "r"(a[0]), "r"(a[1]), "r"(a[2]), "r"(a[3]), "r"(b0), "r"(b1));
}

// ---- per-block smem LUT of stream-K segments per tile ----
__device__ __forceinline__ void build_lut_smem(int* s_lut, int* s_cnt, int T, int Ct, int TC) {
    for (int t = threadIdx.x; t < T; t += blockDim.x) {
        int gb = t * Ct, ge = gb + Ct;
        int u = (int)(((long)(gb + 1) * GRID_G - 1) / TC);
        int cnt = 0;
        for (;;) {
            int u0 = (int)((long)u * TC / GRID_G);
            int seg = t - u0 / Ct;
            s_lut[t * LUT_W + cnt] = 2 * u + seg;
            cnt++;
            int u1 = (int)((long)(u + 1) * TC / GRID_G);
            if (u1 >= ge) break;
            u++;
        }
        s_cnt[t] = cnt;
    }
    __syncthreads();
}

__device__ __forceinline__ float4 sum_tile4(const float* __restrict__ P, const int* s_lut,
                                            const int* s_cnt, int t, int lr, int lc) {
    int cnt = s_cnt[t];
    const int* lp = s_lut + t * LUT_W;
    float4 s = make_float4(0.f, 0.f, 0.f, 0.f);
    for (int j = 0; j < cnt; j++) {
        float4 v = *reinterpret_cast<const float4*>(P + (size_t)lp[j] * 16384 + lr * 128 + lc);
        s.x += v.x; s.y += v.y; s.z += v.z; s.w += v.w;
    }
    return s;
}

// ==================== adj-mix + hi/lo convert (float4) ====================
__global__ void adjmix_convert_kernel(const float* __restrict__ in,
                                      const float* __restrict__ adj,
                                      __nv_bfloat16* __restrict__ hi,
                                      __nv_bfloat16* __restrict__ lo, int F) {
    int t = blockIdx.x * blockDim.x + threadIdx.x;
    int F4 = F >> 2;
    if (t >= B_ * F4) return;
    int b = t / F4, f = (t % F4) * 4;
    float xv[N_][4];
#pragma unroll
    for (int m = 0; m < N_; m++) {
        float4 v = *reinterpret_cast<const float4*>(in + ((size_t)b * N_ + m) * F + f);
        xv[m][0] = v.x; xv[m][1] = v.y; xv[m][2] = v.z; xv[m][3] = v.w;
    }
#pragma unroll
    for (int n = 0; n < N_; n++) {
        float s[4] = {0.f, 0.f, 0.f, 0.f};
#pragma unroll
        for (int m = 0; m < N_; m++) {
            float a = adj[n * N_ + m];
#pragma unroll
            for (int k = 0; k < 4; k++) s[k] += a * xv[m][k];
        }
        __nv_bfloat16 h0, l0, h1, l1;
        split_bf16(s[0], h0, l0); split_bf16(s[1], h1, l1);
        __nv_bfloat162 p0; p0.x = h0; p0.y = h1;
        __nv_bfloat162 q0; q0.x = l0; q0.y = l1;
        split_bf16(s[2], h0, l0); split_bf16(s[3], h1, l1);
        __nv_bfloat162 p1; p1.x = h0; p1.y = h1;
        __nv_bfloat162 q1; q1.x = l0; q1.y = l1;
        *reinterpret_cast<uint2*>(hi + ((size_t)b * N_ + n) * F + f) =
            make_uint2(*reinterpret_cast<uint32_t*>(&p0), *reinterpret_cast<uint32_t*>(&p1));
        *reinterpret_cast<uint2*>(lo + ((size_t)b * N_ + n) * F + f) =
            make_uint2(*reinterpret_cast<uint32_t*>(&q0), *reinterpret_cast<uint32_t*>(&q1));
    }
}

// ==================== HMMA GEMM: stream-K balanced chunk ranges ====================
// Smem: Ahi@0, Alo@20480 (80B rows), Bhi@40960, Blo@58368 (272B rows). 75776 B.
#define SMEM_TOTAL_GEMM 75776
__global__ void __launch_bounds__(256, 2)
gemm_sk(const __nv_bfloat16* __restrict__ A_hi, const __nv_bfloat16* __restrict__ A_lo,
        const float* __restrict__ W, float* __restrict__ P,
        int Nw, int K, int NTx, int T, int Ct) {
    extern __shared__ __align__(16) uint8_t smem[];
    const uint32_t base = smem_u32(smem);
    const uint32_t oAhi = 0, oAlo = 20480, oBhi = 40960, oBlo = 58368;
    const uint32_t strA = 10240, strB = 8704;

    const int G = gridDim.x;
    const int TC = T * Ct;
    const int u = blockIdx.x;
    const int g0 = (int)((long)u * TC / G);
    const int g1 = (int)((long)(u + 1) * TC / G);
    const int NC = g1 - g0;

    const int tid = threadIdx.x;
    const int lane = tid & 31, warp = tid >> 5;
    const int wr = warp & 3, wc = warp >> 2;

    const int ar0 = tid >> 2, aq0 = tid & 3;
    const int ar1 = (tid + 256) >> 2, aq1 = (tid + 256) & 3;
    int wk[4], wq[4];
#pragma unroll
    for (int i = 0; i < 4; i++) {
        int idx = tid + i * 256;
        wk[i] = idx >> 5; wq[i] = idx & 31;
    }

    const int selRow = (lane & 7) + ((lane >> 3) & 1) * 8;
    const int selHi = (lane >> 4) & 1;
    const uint32_t aOff = (uint32_t)((wr * 32 + selRow) * 80 + selHi * 16);
    const uint32_t bOff = (uint32_t)(selRow * 272 + wc * 128 + selHi * 16);

    float acc[2][8][4] = {};
    float4 wreg[4];

    auto stageA = [&](int g, int buf) {
        int t = g / Ct, c = g - t * Ct;
        int row0 = (t / NTx) * 128;
        int kk = c * 32;
        uint32_t da = base + oAhi + buf * strA;
        uint32_t dl = base + oAlo + buf * strA;
        cp_async16(da + ar0 * 80 + aq0 * 16, A_hi + (size_t)(row0 + ar0) * K + kk + aq0 * 8);
        cp_async16(da + ar1 * 80 + aq1 * 16, A_hi + (size_t)(row0 + ar1) * K + kk + aq1 * 8);
        cp_async16(dl + ar0 * 80 + aq0 * 16, A_lo + (size_t)(row0 + ar0) * K + kk + aq0 * 8);
        cp_async16(dl + ar1 * 80 + aq1 * 16, A_lo + (size_t)(row0 + ar1) * K + kk + aq1 * 8);
    };

    auto ldgW = [&](int g) {
        int t = g / Ct, c = g - t * Ct;
        int col0 = (t % NTx) * 128;
        int kk = c * 32;
#pragma unroll
        for (int i = 0; i < 4; i++) {
            int col = col0 + wq[i] * 4;
            const float* src = W + (size_t)(kk + wk[i]) * Nw + col;
            if (col + 3 < Nw) {
                wreg[i] = *reinterpret_cast<const float4*>(src);
            } else {
                wreg[i].x = (col + 0 < Nw) ? src[0] : 0.f;
                wreg[i].y = (col + 1 < Nw) ? src[1] : 0.f;
                wreg[i].z = (col + 2 < Nw) ? src[2] : 0.f;
                wreg[i].w = (col + 3 < Nw) ? src[3] : 0.f;
            }
        }
    };

    auto convertW = [&](int buf) {
#pragma unroll
        for (int i = 0; i < 4; i++) {
            float4 v = wreg[i];
            __nv_bfloat16 h0, l0, h1, l1, h2, l2, h3, l3;
            split_bf16(v.x, h0, l0); split_bf16(v.y, h1, l1);
            split_bf16(v.z, h2, l2); split_bf16(v.w, h3, l3);
            __nv_bfloat162 hA, hB, lA, lB;
            hA.x = h0; hA.y = h1; hB.x = h2; hB.y = h3;
            lA.x = l0; lA.y = l1; lB.x = l2; lB.y = l3;
            uint2 hp = make_uint2(*reinterpret_cast<uint32_t*>(&hA),
                                  *reinterpret_cast<uint32_t*>(&hB));
            uint2 lp = make_uint2(*reinterpret_cast<uint32_t*>(&lA),
                                  *reinterpret_cast<uint32_t*>(&lB));
            uint32_t off = (uint32_t)(wk[i] * 272 + wq[i] * 8);
            *reinterpret_cast<uint2*>(smem + (oBhi + buf * strB) + off) = hp;
            *reinterpret_cast<uint2*>(smem + (oBlo + buf * strB) + off) = lp;
        }
    };

    const int g = lane >> 2, tg = lane & 3;
    int seg = 0;
    auto flush = [&]() {
        float* up = P + (size_t)(2 * u + seg) * 16384;
#pragma unroll
        for (int mi = 0; mi < 2; mi++)
#pragma unroll
            for (int half = 0; half < 2; half++) {
                int lr = wr * 32 + mi * 16 + g + half * 8;
                float* rowp = up + lr * 128 + wc * 64;
#pragma unroll
                for (int ni = 0; ni < 8; ni++)
                    *reinterpret_cast<float2*>(rowp + ni * 8 + tg * 2) =
                        make_float2(acc[mi][ni][half * 2], acc[mi][ni][half * 2 + 1]);
            }
        seg++;
#pragma unroll
        for (int mi = 0; mi < 2; mi++)
#pragma unroll
            for (int ni = 0; ni < 8; ni++)
#pragma unroll
                for (int k2 = 0; k2 < 4; k2++) acc[mi][ni][k2] = 0.f;
    };

    // prologue
    stageA(g0, 0);
    cp_commit();
    ldgW(g0);
    convertW(0);
    if (NC > 1) ldgW(g0 + 1);
    cp_wait0();
    __syncthreads();
    if (NC > 1) { stageA(g0 + 1, 1); cp_commit(); }

    for (int li = 0; li < NC; li++) {
        const int gc = g0 + li;
        const int buf = li & 1;
        const uint32_t ah = base + oAhi + buf * strA, al = base + oAlo + buf * strA;
        const uint32_t bh = base + oBhi + buf * strB, bl = base + oBlo + buf * strB;

#pragma unroll
        for (int ks = 0; ks < 2; ks++) {
            uint32_t faH[2][4], faL[2][4], fb[4][4];
            ldsm_x4(faH[0], ah + aOff + ks * 32);
            ldsm_x4(faH[1], ah + aOff + 1280 + ks * 32);
            ldsm_x4(faL[0], al + aOff + ks * 32);
            ldsm_x4(faL[1], al + aOff + 1280 + ks * 32);
#pragma unroll
            for (int p = 0; p < 4; p++) ldsm_x4_t(fb[p], bh + bOff + ks * 4352 + p * 32);
#pragma unroll
            for (int mi = 0; mi < 2; mi++)
#pragma unroll
                for (int p = 0; p < 4; p++) {
                    mma16816(acc[mi][2 * p], faH[mi], fb[p][0], fb[p][1]);
                    mma16816(acc[mi][2 * p + 1], faH[mi], fb[p][2], fb[p][3]);
                }
#pragma unroll
            for (int mi = 0; mi < 2; mi++)
#pragma unroll
                for (int p = 0; p < 4; p++) {
                    mma16816(acc[mi][2 * p], faL[mi], fb[p][0], fb[p][1]);
                    mma16816(acc[mi][2 * p + 1], faL[mi], fb[p][2], fb[p][3]);
                }
#pragma unroll
            for (int p = 0; p < 4; p++) ldsm_x4_t(fb[p], bl + bOff + ks * 4352 + p * 32);
#pragma unroll
            for (int mi = 0; mi < 2; mi++)
#pragma unroll
                for (int p = 0; p < 4; p++) {
                    mma16816(acc[mi][2 * p], faH[mi], fb[p][0], fb[p][1]);
                    mma16816(acc[mi][2 * p + 1], faH[mi], fb[p][2], fb[p][3]);
                }
        }

        if (gc + 1 == g1 || (gc + 1) % Ct == 0) flush();

        if (li + 1 < NC) convertW(buf ^ 1);
        cp_wait0();
        __syncthreads();
        if (li + 2 < NC) { ldgW(g0 + li + 2); stageA(g0 + li + 2, buf); cp_commit(); }
    }
}

// ==================== reduce epilogues (smem LUT, float4) ====================
__global__ void reduce_relu_adjmix_convert_kernel(const float* __restrict__ P,
                                                  const float* __restrict__ adj,
                                                  __nv_bfloat16* __restrict__ hi,
                                                  __nv_bfloat16* __restrict__ lo,
                                                  int F, int NTx, int T, int Ct, int TC) {
    __shared__ int s_lut[MAX_T * LUT_W];
    __shared__ int s_cnt[MAX_T];
    build_lut_smem(s_lut, s_cnt, T, Ct, TC);

    int t = blockIdx.x * blockDim.x + threadIdx.x;
    int F4 = F >> 2;
    if (t >= B_ * F4) return;
    int b = t / F4, f = (t % F4) * 4;
    float hv[N_][4];
#pragma unroll
    for (int m = 0; m < N_; m++) {
        int row = b * N_ + m;
        int tile = (row >> 7) * NTx + (f >> 7);
        float4 v = sum_tile4(P, s_lut, s_cnt, tile, row & 127, f & 127);
        hv[m][0] = fmaxf(v.x, 0.f); hv[m][1] = fmaxf(v.y, 0.f);
        hv[m][2] = fmaxf(v.z, 0.f); hv[m][3] = fmaxf(v.w, 0.f);
    }
#pragma unroll
    for (int n = 0; n < N_; n++) {
        float s[4] = {0.f, 0.f, 0.f, 0.f};
#pragma unroll
        for (int m = 0; m < N_; m++) {
            float a = adj[n * N_ + m];
#pragma unroll
            for (int k = 0; k < 4; k++) s[k] += a * hv[m][k];
        }
        __nv_bfloat16 h0, l0, h1, l1;
        split_bf16(s[0], h0, l0); split_bf16(s[1], h1, l1);
        __nv_bfloat162 p0; p0.x = h0; p0.y = h1;
        __nv_bfloat162 q0; q0.x = l0; q0.y = l1;
        split_bf16(s[2], h0, l0); split_bf16(s[3], h1, l1);
        __nv_bfloat162 p1; p1.x = h0; p1.y = h1;
        __nv_bfloat162 q1; q1.x = l0; q1.y = l1;
        *reinterpret_cast<uint2*>(hi + ((size_t)b * N_ + n) * F + f) =
            make_uint2(*reinterpret_cast<uint32_t*>(&p0), *reinterpret_cast<uint32_t*>(&p1));
        *reinterpret_cast<uint2*>(lo + ((size_t)b * N_ + n) * F + f) =
            make_uint2(*reinterpret_cast<uint32_t*>(&q0), *reinterpret_cast<uint32_t*>(&q1));
    }
}

__global__ void reduce_convert_kernel(const float* __restrict__ P, int Mrows, int F,
                                      __nv_bfloat16* __restrict__ hi,
                                      __nv_bfloat16* __restrict__ lo,
                                      int NTx, int T, int Ct, int TC) {
    __shared__ int s_lut[MAX_T * LUT_W];
    __shared__ int s_cnt[MAX_T];
    build_lut_smem(s_lut, s_cnt, T, Ct, TC);

    int t = blockIdx.x * blockDim.x + threadIdx.x;
    int F4 = F >> 2;
    if (t >= Mrows * F4) return;
    int row = t / F4, f = (t % F4) * 4;
    int tile = (row >> 7) * NTx + (f >> 7);
    float4 s = sum_tile4(P, s_lut, s_cnt, tile, row & 127, f & 127);
    __nv_bfloat16 h0, l0, h1, l1;
    split_bf16(s.x, h0, l0); split_bf16(s.y, h1, l1);
    __nv_bfloat162 p0; p0.x = h0; p0.y = h1;
    __nv_bfloat162 q0; q0.x = l0; q0.y = l1;
    split_bf16(s.z, h0, l0); split_bf16(s.w, h1, l1);
    __nv_bfloat162 p1; p1.x = h0; p1.y = h1;
    __nv_bfloat162 q1; q1.x = l0; q1.y = l1;
    *reinterpret_cast<uint2*>(hi + (size_t)row * F + f) =
        make_uint2(*reinterpret_cast<uint32_t*>(&p0), *reinterpret_cast<uint32_t*>(&p1));
    *reinterpret_cast<uint2*>(lo + (size_t)row * F + f) =
        make_uint2(*reinterpret_cast<uint32_t*>(&q0), *reinterpret_cast<uint32_t*>(&q1));
}

__global__ void reduce_bias_convert_kernel(const float* __restrict__ P, int Mrows, int F,
                                           const float* __restrict__ bias,
                                           __nv_bfloat16* __restrict__ hi,
                                           __nv_bfloat16* __restrict__ lo,
                                           int NTx, int T, int Ct, int TC) {
    __shared__ int s_lut[MAX_T * LUT_W];
    __shared__ int s_cnt[MAX_T];
    build_lut_smem(s_lut, s_cnt, T, Ct, TC);

    int t = blockIdx.x * blockDim.x + threadIdx.x;
    int F4 = F >> 2;
    if (t >= Mrows * F4) return;
    int row = t / F4, f = (t % F4) * 4;
    int tile = (row >> 7) * NTx + (f >> 7);
    float4 s = sum_tile4(P, s_lut, s_cnt, tile, row & 127, f & 127);
    float4 bv = *reinterpret_cast<const float4*>(bias + f);
    s.x += bv.x; s.y += bv.y; s.z += bv.z; s.w += bv.w;
    __nv_bfloat16 h0, l0, h1, l1;
    split_bf16(s.x, h0, l0); split_bf16(s.y, h1, l1);
    __nv_bfloat162 p0; p0.x = h0; p0.y = h1;
    __nv_bfloat162 q0; q0.x = l0; q0.y = l1;
    split_bf16(s.z, h0, l0); split_bf16(s.w, h1, l1);
    __nv_bfloat162 p1; p1.x = h0; p1.y = h1;
    __nv_bfloat162 q1; q1.x = l0; q1.y = l1;
    *reinterpret_cast<uint2*>(hi + (size_t)row * F + f) =
        make_uint2(*reinterpret_cast<uint32_t*>(&p0), *reinterpret_cast<uint32_t*>(&p1));
    *reinterpret_cast<uint2*>(lo + (size_t)row * F + f) =
        make_uint2(*reinterpret_cast<uint32_t*>(&q0), *reinterpret_cast<uint32_t*>(&q1));
}

__global__ void reduce_bias_out_kernel(const float* __restrict__ P,
                                       const float* __restrict__ bias,
                                       float* __restrict__ out,
                                       int NTx, int T, int Ct, int TC) {
    __shared__ int s_lut[MAX_T * LUT_W];
    __shared__ int s_cnt[MAX_T];
    build_lut_smem(s_lut, s_cnt, T, Ct, TC);

    int t = blockIdx.x * blockDim.x + threadIdx.x;
    const int C4 = C_ >> 2;   // 250
    if (t >= B_ * C4) return;
    int b = t / C4, n = (t % C4) * 4;
    int tile = (b >> 7) * NTx + (n >> 7);
    float4 s = sum_tile4(P, s_lut, s_cnt, tile, b & 127, n & 127);
    float4 bv = *reinterpret_cast<const float4*>(bias + n);
    *reinterpret_cast<float4*>(out + (size_t)b * C_ + n) =
        make_float4(s.x + bv.x, s.y + bv.y, s.z + bv.z, s.w + bv.w);
}

// ==================== prototype EMA (closed form), parallel metadata ====================
__global__ void class_meta_kernel(const int* __restrict__ target) {  // 1 block, 1024 thr
    __shared__ int cnt[1024];
    __shared__ int scan[1024];
    __shared__ int t_s[B_];
    __shared__ int rank_s[B_];
    int tid = threadIdx.x;
    cnt[tid] = 0;
    __syncthreads();
    if (tid < B_) t_s[tid] = target[tid];
    __syncthreads();
    if (tid < B_) {
        int c = t_s[tid], r = 0;
        for (int j = 0; j < tid; j++) r += (t_s[j] == c) ? 1 : 0;
        rank_s[tid] = r;
        atomicAdd(&cnt[c], 1);
    }
    __syncthreads();
    if (tid < C_) g_scale[tid] = powf(PROTO_M, (float)cnt[tid]);
    scan[tid] = cnt[tid];
    __syncthreads();
    for (int ofs = 1; ofs < 1024; ofs <<= 1) {
        int v = (tid >= ofs) ? scan[tid - ofs] : 0;
        __syncthreads();
        scan[tid] += v;
        __syncthreads();
    }
    if (tid < C_) g_off[tid] = scan[tid] - cnt[tid];
    if (tid == 0) g_off[C_] = B_;
    __syncthreads();
    if (tid < B_) {
        int c = t_s[tid];
        int p = (scan[c] - cnt[c]) + rank_s[tid];
        g_idx[p] = tid;
        g_w[p] = (1.0f - PROTO_M) * powf(PROTO_M, (float)(cnt[c] - 1 - rank_s[tid]));
    }
}

__global__ void proto_update_kernel(const float* __restrict__ x,
                                    const float* __restrict__ protos,
                                    float* __restrict__ out) {
    int t = blockIdx.x * blockDim.x + threadIdx.x;
    const int D4 = D_ / 4;
    if (t >= C_ * D4) return;
    int c = t / D4, d4 = t % D4;
    float s = g_scale[c];
    float4 v[N_];
#pragma unroll
    for (int n = 0; n < N_; n++) {
        float4 p = *reinterpret_cast<const float4*>(protos + ((size_t)c * N_ + n) * D_ + d4 * 4);
        v[n] = make_float4(p.x * s, p.y * s, p.z * s, p.w * s);
    }
    int e = g_off[c + 1];
    for (int j = g_off[c]; j < e; j++) {
        int i = g_idx[j];
        float w = g_w[j];
#pragma unroll
        for (int n = 0; n < N_; n++) {
            float4 xv = *reinterpret_cast<const float4*>(x + ((size_t)i * N_ + n) * D_ + d4 * 4);
            v[n].x += w * xv.x; v[n].y += w * xv.y;
            v[n].z += w * xv.z; v[n].w += w * xv.w;
        }
    }
    float4 nrm4 = make_float4(0.f, 0.f, 0.f, 0.f);
#pragma unroll
    for (int n = 0; n < N_; n++) {
        nrm4.x += v[n].x * v[n].x; nrm4.y += v[n].y * v[n].y;
        nrm4.z += v[n].z * v[n].z; nrm4.w += v[n].w * v[n].w;
    }
    float4 inv = make_float4(1.f / fmaxf(sqrtf(nrm4.x), EPS_), 1.f / fmaxf(sqrtf(nrm4.y), EPS_),
                             1.f / fmaxf(sqrtf(nrm4.z), EPS_), 1.f / fmaxf(sqrtf(nrm4.w), EPS_));
#pragma unroll
    for (int n = 0; n < N_; n++) {
        float4 o = make_float4(v[n].x * inv.x, v[n].y * inv.y, v[n].z * inv.z, v[n].w * inv.w);
        *reinterpret_cast<float4*>(out + ((size_t)c * N_ + n) * D_ + d4 * 4) = o;
    }
}

// ==================== launch ====================
static cudaStream_t make_stream() {
    cudaStream_t s;
    cudaStreamCreateWithFlags(&s, cudaStreamNonBlocking);
    return s;
}
static cudaEvent_t make_event() {
    cudaEvent_t e;
    cudaEventCreateWithFlags(&e, cudaEventDisableTiming);
    return e;
}

extern "C" void kernel_launch(void* const* d_in, const int* in_sizes, int n_in,
                              void* d_out, int out_size) {
    const float* x    = (const float*)d_in[0];
    const int*   tgt  = (const int*)d_in[1];
    const float* prot = (const float*)d_in[2];
    const float* adj  = (const float*)d_in[3];
    const float* W1   = (const float*)d_in[4];
    const float* W2   = (const float*)d_in[5];
    const float* Wg   = (const float*)d_in[6];
    const float* bg   = (const float*)d_in[7];
    const float* Wc   = (const float*)d_in[8];
    const float* bc   = (const float*)d_in[9];

    float* pred_out  = (float*)d_out;
    float* proto_out = (float*)d_out + (size_t)B_ * C_;

    __nv_bfloat16 *ax_hi, *ax_lo, *ah_hi, *ah_lo, *nd_hi, *nd_lo, *gg_hi, *gg_lo;
    float* part;
    cudaGetSymbolAddress((void**)&ax_hi, g_ax_hi);   cudaGetSymbolAddress((void**)&ax_lo, g_ax_lo);
    cudaGetSymbolAddress((void**)&ah_hi, g_ah_hi);   cudaGetSymbolAddress((void**)&ah_lo, g_ah_lo);
    cudaGetSymbolAddress((void**)&nd_hi, g_nd_hi);   cudaGetSymbolAddress((void**)&nd_lo, g_nd_lo);
    cudaGetSymbolAddress((void**)&gg_hi, g_g_hi);    cudaGetSymbolAddress((void**)&gg_lo, g_g_lo);
    cudaGetSymbolAddress((void**)&part, g_part);

    cudaFuncSetAttribute(gemm_sk, cudaFuncAttributeMaxDynamicSharedMemorySize, SMEM_TOTAL_GEMM);

    // one-time resources (function-local statics; same behavior every call)
    static cudaStream_t s2 = make_stream();
    static cudaEvent_t ev_fork = make_event();
    static cudaEvent_t ev_join = make_event();

    // ---- fork: prototype branch (independent of GEMM chain) on s2 ----
    cudaEventRecord(ev_fork, 0);
    cudaStreamWaitEvent(s2, ev_fork, 0);
    class_meta_kernel<<<1, 1024, 0, s2>>>(tgt);
    proto_update_kernel<<<(C_ * (D_ / 4) + 255) / 256, 256, 0, s2>>>(x, prot, proto_out);
    cudaEventRecord(ev_join, s2);

    // ---- main chain on default stream ----
    adjmix_convert_kernel<<<(B_ * (D_ / 4) + 255) / 256, 256>>>(x, adj, ax_hi, ax_lo, D_);

    // GEMM1: [1280,2048]@W1[2048,1024]. T=80 (10x8), Ct=64, TC=5120.
    gemm_sk<<<GRID_G, 256, SMEM_TOTAL_GEMM>>>(ax_hi, ax_lo, W1, part, H_, D_, 8, 80, 64);
    reduce_relu_adjmix_convert_kernel<<<(B_ * (H_ / 4) + 255) / 256, 256>>>(
        part, adj, ah_hi, ah_lo, H_, 8, 80, 64, 5120);

    // GEMM2: [1280,1024]@W2[1024,2048]. T=160 (10x16), Ct=32, TC=5120.
    gemm_sk<<<GRID_G, 256, SMEM_TOTAL_GEMM>>>(ah_hi, ah_lo, W2, part, D_, H_, 16, 160, 32);
    reduce_convert_kernel<<<(B_ * N_ * (D_ / 4) + 255) / 256, 256>>>(
        part, B_ * N_, D_, nd_hi, nd_lo, 16, 160, 32, 5120);

    // fc_g: [256,10240]@Wg[10240,2048]. T=32 (2x16), Ct=320, TC=10240.
    gemm_sk<<<GRID_G, 256, SMEM_TOTAL_GEMM>>>(nd_hi, nd_lo, Wg, part, D_, N_ * D_, 16, 32, 320);
    reduce_bias_convert_kernel<<<(B_ * (D_ / 4) + 255) / 256, 256>>>(
        part, B_, D_, bg, gg_hi, gg_lo, 16, 32, 320, 10240);

    // fc_cls: [256,2048]@Wc[2048,1000 pad 1024]. T=16 (2x8), Ct=64, TC=1024.
    gemm_sk<<<GRID_G, 256, SMEM_TOTAL_GEMM>>>(gg_hi, gg_lo, Wc, part, C_, D_, 8, 16, 64);
    reduce_bias_out_kernel<<<(B_ * (C_ / 4) + 255) / 256, 256>>>(
        part, bc, pred_out, 8, 16, 64, 1024);

    // ---- join ----
    cudaStreamWaitEvent(0, ev_join, 0);
}

// round 17
// speedup vs baseline: 1.2535x; 1.0276x over previous
#include <cuda_runtime.h>
#include <cuda_bf16.h>
#include <cstdint>

#define B_ 256
#define N_ 5
#define D_ 2048
#define C_ 1000
#define H_ 1024
#define PROTO_M 0.999f
#define EPS_ 1e-12f
#define GRID_G 296
#define LUT_W 24
#define MAX_T 160

// ==================== scratch (static device globals) ====================
__device__ __nv_bfloat16 g_ax_hi[B_ * N_ * D_], g_ax_lo[B_ * N_ * D_];
__device__ __nv_bfloat16 g_ah_hi[B_ * N_ * H_], g_ah_lo[B_ * N_ * H_];
__device__ __nv_bfloat16 g_nd_hi[B_ * N_ * D_], g_nd_lo[B_ * N_ * D_];
__device__ __nv_bfloat16 g_g_hi[B_ * D_], g_g_lo[B_ * D_];
__device__ float g_part[2 * GRID_G * 128 * 128];

__device__ unsigned g_bcnt[8];   // ticket barrier counters (monotonic across replays)

__device__ float g_scale[C_];
__device__ int   g_off[C_ + 1];
__device__ int   g_idx[B_];
__device__ float g_w[B_];

// ==================== helpers ====================
__device__ __forceinline__ void split_bf16(float v, __nv_bfloat16& hi, __nv_bfloat16& lo) {
    hi = __float2bfloat16_rn(v);
    lo = __float2bfloat16_rn(v - __bfloat162float(hi));
}
__device__ __forceinline__ uint32_t smem_u32(const void* p) {
    uint32_t a;
    asm("{ .reg .u64 t; cvta.to.shared.u64 t, %1; cvt.u32.u64 %0, t; }" : "=r"(a) : "l"(p));
    return a;
}
__device__ __forceinline__ void cp_async16(uint32_t dst, const void* src) {
    asm volatile("cp.async.cg.shared.global [%0], [%1], 16;" :: "r"(dst), "l"(src));
}
__device__ __forceinline__ void cp_commit() { asm volatile("cp.async.commit_group;" ::: "memory"); }
__device__ __forceinline__ void cp_wait0() { asm volatile("cp.async.wait_group 0;" ::: "memory"); }

__device__ __forceinline__ void ldsm_x4(uint32_t* r, uint32_t addr) {
    asm volatile("ldmatrix.sync.aligned.m8n8.x4.shared.b16 {%0,%1,%2,%3}, [%4];"
        : "=r"(r[0]), "=r"(r[1]), "=r"(r[2]), "=r"(r[3]) : "r"(addr));
}
__device__ __forceinline__ void ldsm_x4_t(uint32_t* r, uint32_t addr) {
    asm volatile("ldmatrix.sync.aligned.m8n8.x4.trans.shared.b16 {%0,%1,%2,%3}, [%4];"
        : "=r"(r[0]), "=r"(r[1]), "=r"(r[2]), "=r"(r[3]) : "r"(addr));
}
__device__ __forceinline__ void mma16816(float* c, const uint32_t* a, uint32_t b0, uint32_t b1) {
    asm volatile(
        "mma.sync.aligned.m16n8k16.row.col.f32.bf16.bf16.f32 "
        "{%0,%1,%2,%3}, {%4,%5,%6,%7}, {%8,%9}, {%0,%1,%2,%3};"
        : "+f"(c[0]), "+f"(c[1]), "+f"(c[2]), "+f"(c[3])
        : "r"(a[0]), "r"(a[1]), "r"(a[2]), "r"(a[3]), "r"(b0), "r"(b1));
}

// ---- global ticket barrier (safe across graph replays; all CTAs co-resident) ----
__device__ __forceinline__ void gbar(int i) {
    __syncthreads();
    if (threadIdx.x == 0) {
        __threadfence();
        unsigned v = atomicAdd(&g_bcnt[i], 1u) + 1u;
        unsigned tgt = ((v + GRID_G - 1u) / GRID_G) * GRID_G;
        while (atomicAdd(&g_bcnt[i], 0u) < tgt) { }
        __threadfence();
    }
    __syncthreads();
}

// ==================== phase: class metadata (block 0, 256 threads) ====================
__device__ __noinline__ void phase_meta(const int* __restrict__ target, uint8_t* sm) {
    int* cnt = (int*)sm;          // [1024]
    int* co  = cnt + 1024;        // [1024]
    int* ts  = co + 1024;         // [256]
    int* rs  = ts + 256;          // [256]
    int* sc  = rs + 256;          // [256]
    int* ps  = sc + 256;          // [256]
    int tid = threadIdx.x;
    for (int c = tid; c < 1024; c += 256) cnt[c] = 0;
    __syncthreads();
    ts[tid] = target[tid];
    __syncthreads();
    int c0 = ts[tid], r = 0;
    for (int j = 0; j < tid; j++) r += (ts[j] == c0) ? 1 : 0;
    rs[tid] = r;
    atomicAdd(&cnt[c0], 1);
    __syncthreads();
    for (int c = tid; c < C_; c += 256) g_scale[c] = powf(PROTO_M, (float)cnt[c]);
    int s = 0;
#pragma unroll
    for (int k = 0; k < 4; k++) s += cnt[4 * tid + k];
    ps[tid] = s; sc[tid] = s;
    __syncthreads();
    for (int o = 1; o < 256; o <<= 1) {
        int v = (tid >= o) ? sc[tid - o] : 0;
        __syncthreads();
        sc[tid] += v;
        __syncthreads();
    }
    int off = sc[tid] - ps[tid];
#pragma unroll
    for (int k = 0; k < 4; k++) {
        int c = 4 * tid + k;
        co[c] = off;
        if (c < C_) g_off[c] = off;
        off += cnt[c];
    }
    if (tid == 0) g_off[C_] = B_;
    __syncthreads();
    int p = co[c0] + rs[tid];
    g_idx[p] = tid;
    g_w[p] = (1.0f - PROTO_M) * powf(PROTO_M, (float)(cnt[c0] - 1 - rs[tid]));
}

// ==================== phase: adj-mix + hi/lo convert (blocks 1..295) ====================
__device__ __noinline__ void phase_adjmix(const float* __restrict__ in,
                                          const float* __restrict__ adj,
                                          __nv_bfloat16* __restrict__ hi,
                                          __nv_bfloat16* __restrict__ lo) {
    const int F = D_, F4 = D_ / 4;
    const int stride = (GRID_G - 1) * 256;
    for (int t = (blockIdx.x - 1) * 256 + threadIdx.x; t < B_ * F4; t += stride) {
        int b = t / F4, f = (t % F4) * 4;
        float xv[N_][4];
#pragma unroll
        for (int m = 0; m < N_; m++) {
            float4 v = *reinterpret_cast<const float4*>(in + ((size_t)b * N_ + m) * F + f);
            xv[m][0] = v.x; xv[m][1] = v.y; xv[m][2] = v.z; xv[m][3] = v.w;
        }
#pragma unroll
        for (int n = 0; n < N_; n++) {
            float s[4] = {0.f, 0.f, 0.f, 0.f};
#pragma unroll
            for (int m = 0; m < N_; m++) {
                float a = adj[n * N_ + m];
#pragma unroll
                for (int k = 0; k < 4; k++) s[k] += a * xv[m][k];
            }
            __nv_bfloat16 h0, l0, h1, l1;
            split_bf16(s[0], h0, l0); split_bf16(s[1], h1, l1);
            __nv_bfloat162 p0; p0.x = h0; p0.y = h1;
            __nv_bfloat162 q0; q0.x = l0; q0.y = l1;
            split_bf16(s[2], h0, l0); split_bf16(s[3], h1, l1);
            __nv_bfloat162 p1; p1.x = h0; p1.y = h1;
            __nv_bfloat162 q1; q1.x = l0; q1.y = l1;
            *reinterpret_cast<uint2*>(hi + ((size_t)b * N_ + n) * F + f) =
                make_uint2(*reinterpret_cast<uint32_t*>(&p0), *reinterpret_cast<uint32_t*>(&p1));
            *reinterpret_cast<uint2*>(lo + ((size_t)b * N_ + n) * F + f) =
                make_uint2(*reinterpret_cast<uint32_t*>(&q0), *reinterpret_cast<uint32_t*>(&q1));
        }
    }
}

// ==================== phase: stream-K HMMA GEMM (identical to round-16 gemm_sk) ====
__device__ __noinline__ void phase_gemm(const __nv_bfloat16* __restrict__ A_hi,
                                        const __nv_bfloat16* __restrict__ A_lo,
                                        const float* __restrict__ W, float* __restrict__ P,
                                        int Nw, int K, int NTx, int T, int Ct,
                                        uint8_t* smem) {
    const uint32_t base = smem_u32(smem);
    const uint32_t oAhi = 0, oAlo = 20480, oBhi = 40960, oBlo = 58368;
    const uint32_t strA = 10240, strB = 8704;

    const int G = GRID_G;
    const int TC = T * Ct;
    const int u = blockIdx.x;
    const int g0 = (int)((long)u * TC / G);
    const int g1 = (int)((long)(u + 1) * TC / G);
    const int NC = g1 - g0;

    const int tid = threadIdx.x;
    const int lane = tid & 31, warp = tid >> 5;
    const int wr = warp & 3, wc = warp >> 2;

    const int ar0 = tid >> 2, aq0 = tid & 3;
    const int ar1 = (tid + 256) >> 2, aq1 = (tid + 256) & 3;
    int wk[4], wq[4];
#pragma unroll
    for (int i = 0; i < 4; i++) {
        int idx = tid + i * 256;
        wk[i] = idx >> 5; wq[i] = idx & 31;
    }

    const int selRow = (lane & 7) + ((lane >> 3) & 1) * 8;
    const int selHi = (lane >> 4) & 1;
    const uint32_t aOff = (uint32_t)((wr * 32 + selRow) * 80 + selHi * 16);
    const uint32_t bOff = (uint32_t)(selRow * 272 + wc * 128 + selHi * 16);

    float acc[2][8][4] = {};
    float4 wreg[4];

    auto stageA = [&](int g, int buf) {
        int t = g / Ct, c = g - t * Ct;
        int row0 = (t / NTx) * 128;
        int kk = c * 32;
        uint32_t da = base + oAhi + buf * strA;
        uint32_t dl = base + oAlo + buf * strA;
        cp_async16(da + ar0 * 80 + aq0 * 16, A_hi + (size_t)(row0 + ar0) * K + kk + aq0 * 8);
        cp_async16(da + ar1 * 80 + aq1 * 16, A_hi + (size_t)(row0 + ar1) * K + kk + aq1 * 8);
        cp_async16(dl + ar0 * 80 + aq0 * 16, A_lo + (size_t)(row0 + ar0) * K + kk + aq0 * 8);
        cp_async16(dl + ar1 * 80 + aq1 * 16, A_lo + (size_t)(row0 + ar1) * K + kk + aq1 * 8);
    };

    auto ldgW = [&](int g) {
        int t = g / Ct, c = g - t * Ct;
        int col0 = (t % NTx) * 128;
        int kk = c * 32;
#pragma unroll
        for (int i = 0; i < 4; i++) {
            int col = col0 + wq[i] * 4;
            const float* src = W + (size_t)(kk + wk[i]) * Nw + col;
            if (col + 3 < Nw) {
                wreg[i] = *reinterpret_cast<const float4*>(src);
            } else {
                wreg[i].x = (col + 0 < Nw) ? src[0] : 0.f;
                wreg[i].y = (col + 1 < Nw) ? src[1] : 0.f;
                wreg[i].z = (col + 2 < Nw) ? src[2] : 0.f;
                wreg[i].w = (col + 3 < Nw) ? src[3] : 0.f;
            }
        }
    };

    auto convertW = [&](int buf) {
#pragma unroll
        for (int i = 0; i < 4; i++) {
            float4 v = wreg[i];
            __nv_bfloat16 h0, l0, h1, l1, h2, l2, h3, l3;
            split_bf16(v.x, h0, l0); split_bf16(v.y, h1, l1);
            split_bf16(v.z, h2, l2); split_bf16(v.w, h3, l3);
            __nv_bfloat162 hA, hB, lA, lB;
            hA.x = h0; hA.y = h1; hB.x = h2; hB.y = h3;
            lA.x = l0; lA.y = l1; lB.x = l2; lB.y = l3;
            uint2 hp = make_uint2(*reinterpret_cast<uint32_t*>(&hA),
                                  *reinterpret_cast<uint32_t*>(&hB));
            uint2 lp = make_uint2(*reinterpret_cast<uint32_t*>(&lA),
                                  *reinterpret_cast<uint32_t*>(&lB));
            uint32_t off = (uint32_t)(wk[i] * 272 + wq[i] * 8);
            *reinterpret_cast<uint2*>(smem + (oBhi + buf * strB) + off) = hp;
            *reinterpret_cast<uint2*>(smem + (oBlo + buf * strB) + off) = lp;
        }
    };

    const int g = lane >> 2, tg = lane & 3;
    int seg = 0;
    auto flush = [&]() {
        float* up = P + (size_t)(2 * u + seg) * 16384;
#pragma unroll
        for (int mi = 0; mi < 2; mi++)
#pragma unroll
            for (int half = 0; half < 2; half++) {
                int lr = wr * 32 + mi * 16 + g + half * 8;
                float* rowp = up + lr * 128 + wc * 64;
#pragma unroll
                for (int ni = 0; ni < 8; ni++)
                    *reinterpret_cast<float2*>(rowp + ni * 8 + tg * 2) =
                        make_float2(acc[mi][ni][half * 2], acc[mi][ni][half * 2 + 1]);
            }
        seg++;
#pragma unroll
        for (int mi = 0; mi < 2; mi++)
#pragma unroll
            for (int ni = 0; ni < 8; ni++)
#pragma unroll
                for (int k2 = 0; k2 < 4; k2++) acc[mi][ni][k2] = 0.f;
    };

    stageA(g0, 0);
    cp_commit();
    ldgW(g0);
    convertW(0);
    if (NC > 1) ldgW(g0 + 1);
    cp_wait0();
    __syncthreads();
    if (NC > 1) { stageA(g0 + 1, 1); cp_commit(); }

    for (int li = 0; li < NC; li++) {
        const int gc = g0 + li;
        const int buf = li & 1;
        const uint32_t ah = base + oAhi + buf * strA, al = base + oAlo + buf * strA;
        const uint32_t bh = base + oBhi + buf * strB, bl = base + oBlo + buf * strB;

#pragma unroll
        for (int ks = 0; ks < 2; ks++) {
            uint32_t faH[2][4], faL[2][4], fb[4][4];
            ldsm_x4(faH[0], ah + aOff + ks * 32);
            ldsm_x4(faH[1], ah + aOff + 1280 + ks * 32);
            ldsm_x4(faL[0], al + aOff + ks * 32);
            ldsm_x4(faL[1], al + aOff + 1280 + ks * 32);
#pragma unroll
            for (int p = 0; p < 4; p++) ldsm_x4_t(fb[p], bh + bOff + ks * 4352 + p * 32);
#pragma unroll
            for (int mi = 0; mi < 2; mi++)
#pragma unroll
                for (int p = 0; p < 4; p++) {
                    mma16816(acc[mi][2 * p], faH[mi], fb[p][0], fb[p][1]);
                    mma16816(acc[mi][2 * p + 1], faH[mi], fb[p][2], fb[p][3]);
                }
#pragma unroll
            for (int mi = 0; mi < 2; mi++)
#pragma unroll
                for (int p = 0; p < 4; p++) {
                    mma16816(acc[mi][2 * p], faL[mi], fb[p][0], fb[p][1]);
                    mma16816(acc[mi][2 * p + 1], faL[mi], fb[p][2], fb[p][3]);
                }
#pragma unroll
            for (int p = 0; p < 4; p++) ldsm_x4_t(fb[p], bl + bOff + ks * 4352 + p * 32);
#pragma unroll
            for (int mi = 0; mi < 2; mi++)
#pragma unroll
                for (int p = 0; p < 4; p++) {
                    mma16816(acc[mi][2 * p], faH[mi], fb[p][0], fb[p][1]);
                    mma16816(acc[mi][2 * p + 1], faH[mi], fb[p][2], fb[p][3]);
                }
        }

        if (gc + 1 == g1 || (gc + 1) % Ct == 0) flush();

        if (li + 1 < NC) convertW(buf ^ 1);
        cp_wait0();
        __syncthreads();
        if (li + 2 < NC) { ldgW(g0 + li + 2); stageA(g0 + li + 2, buf); cp_commit(); }
    }
}

// ==================== reduce helpers (smem LUT, float4) ====================
__device__ __forceinline__ void build_lut_smem(int* s_lut, int* s_cnt, int T, int Ct, int TC) {
    for (int t = threadIdx.x; t < T; t += 256) {
        int gb = t * Ct, ge = gb + Ct;
        int u = (int)(((long)(gb + 1) * GRID_G - 1) / TC);
        int cnt = 0;
        for (;;) {
            int u0 = (int)((long)u * TC / GRID_G);
            int seg = t - u0 / Ct;
            s_lut[t * LUT_W + cnt] = 2 * u + seg;
            cnt++;
            int u1 = (int)((long)(u + 1) * TC / GRID_G);
            if (u1 >= ge) break;
            u++;
        }
        s_cnt[t] = cnt;
    }
    __syncthreads();
}
__device__ __forceinline__ float4 sum_tile4(const float* __restrict__ P, const int* s_lut,
                                            const int* s_cnt, int t, int lr, int lc) {
    int cnt = s_cnt[t];
    const int* lp = s_lut + t * LUT_W;
    float4 s = make_float4(0.f, 0.f, 0.f, 0.f);
    for (int j = 0; j < cnt; j++) {
        float4 v = *reinterpret_cast<const float4*>(P + (size_t)lp[j] * 16384 + lr * 128 + lc);
        s.x += v.x; s.y += v.y; s.z += v.z; s.w += v.w;
    }
    return s;
}

// ==================== phase: reduce1 relu+adjmix+convert ====================
__device__ __noinline__ void phase_r1(const float* __restrict__ P,
                                      const float* __restrict__ adj,
                                      __nv_bfloat16* __restrict__ hi,
                                      __nv_bfloat16* __restrict__ lo, uint8_t* sm) {
    int* s_lut = (int*)sm;
    int* s_cnt = s_lut + MAX_T * LUT_W;
    build_lut_smem(s_lut, s_cnt, 80, 64, 5120);
    const int F = H_, F4 = H_ / 4, NTx = 8;
    for (int t = blockIdx.x * 256 + threadIdx.x; t < B_ * F4; t += GRID_G * 256) {
        int b = t / F4, f = (t % F4) * 4;
        float hv[N_][4];
#pragma unroll
        for (int m = 0; m < N_; m++) {
            int row = b * N_ + m;
            int tile = (row >> 7) * NTx + (f >> 7);
            float4 v = sum_tile4(P, s_lut, s_cnt, tile, row & 127, f & 127);
            hv[m][0] = fmaxf(v.x, 0.f); hv[m][1] = fmaxf(v.y, 0.f);
            hv[m][2] = fmaxf(v.z, 0.f); hv[m][3] = fmaxf(v.w, 0.f);
        }
#pragma unroll
        for (int n = 0; n < N_; n++) {
            float s[4] = {0.f, 0.f, 0.f, 0.f};
#pragma unroll
            for (int m = 0; m < N_; m++) {
                float a = adj[n * N_ + m];
#pragma unroll
                for (int k = 0; k < 4; k++) s[k] += a * hv[m][k];
            }
            __nv_bfloat16 h0, l0, h1, l1;
            split_bf16(s[0], h0, l0); split_bf16(s[1], h1, l1);
            __nv_bfloat162 p0; p0.x = h0; p0.y = h1;
            __nv_bfloat162 q0; q0.x = l0; q0.y = l1;
            split_bf16(s[2], h0, l0); split_bf16(s[3], h1, l1);
            __nv_bfloat162 p1; p1.x = h0; p1.y = h1;
            __nv_bfloat162 q1; q1.x = l0; q1.y = l1;
            *reinterpret_cast<uint2*>(hi + ((size_t)b * N_ + n) * F + f) =
                make_uint2(*reinterpret_cast<uint32_t*>(&p0), *reinterpret_cast<uint32_t*>(&p1));
            *reinterpret_cast<uint2*>(lo + ((size_t)b * N_ + n) * F + f) =
                make_uint2(*reinterpret_cast<uint32_t*>(&q0), *reinterpret_cast<uint32_t*>(&q1));
        }
    }
}

// ==================== phase: generic reduce + (bias) + hi/lo convert ====================
__device__ __noinline__ void phase_rconv(const float* __restrict__ P, int Mrows, int F,
                                         const float* __restrict__ bias,
                                         __nv_bfloat16* __restrict__ hi,
                                         __nv_bfloat16* __restrict__ lo,
                                         int NTx, int T, int Ct, int TC, uint8_t* sm) {
    int* s_lut = (int*)sm;
    int* s_cnt = s_lut + MAX_T * LUT_W;
    build_lut_smem(s_lut, s_cnt, T, Ct, TC);
    int F4 = F >> 2;
    for (int t = blockIdx.x * 256 + threadIdx.x; t < Mrows * F4; t += GRID_G * 256) {
        int row = t / F4, f = (t % F4) * 4;
        int tile = (row >> 7) * NTx + (f >> 7);
        float4 s = sum_tile4(P, s_lut, s_cnt, tile, row & 127, f & 127);
        if (bias) {
            float4 bv = *reinterpret_cast<const float4*>(bias + f);
            s.x += bv.x; s.y += bv.y; s.z += bv.z; s.w += bv.w;
        }
        __nv_bfloat16 h0, l0, h1, l1;
        split_bf16(s.x, h0, l0); split_bf16(s.y, h1, l1);
        __nv_bfloat162 p0; p0.x = h0; p0.y = h1;
        __nv_bfloat162 q0; q0.x = l0; q0.y = l1;
        split_bf16(s.z, h0, l0); split_bf16(s.w, h1, l1);
        __nv_bfloat162 p1; p1.x = h0; p1.y = h1;
        __nv_bfloat162 q1; q1.x = l0; q1.y = l1;
        *reinterpret_cast<uint2*>(hi + (size_t)row * F + f) =
            make_uint2(*reinterpret_cast<uint32_t*>(&p0), *reinterpret_cast<uint32_t*>(&p1));
        *reinterpret_cast<uint2*>(lo + (size_t)row * F + f) =
            make_uint2(*reinterpret_cast<uint32_t*>(&q0), *reinterpret_cast<uint32_t*>(&q1));
    }
}

// ==================== phase: final reduce (bias, strip pad) + proto ====================
__device__ __noinline__ void phase_r4(const float* __restrict__ P,
                                      const float* __restrict__ bias,
                                      float* __restrict__ out, uint8_t* sm) {
    int* s_lut = (int*)sm;
    int* s_cnt = s_lut + MAX_T * LUT_W;
    build_lut_smem(s_lut, s_cnt, 16, 64, 1024);
    const int C4 = C_ >> 2, NTx = 8;
    for (int t = blockIdx.x * 256 + threadIdx.x; t < B_ * C4; t += GRID_G * 256) {
        int b = t / C4, n = (t % C4) * 4;
        int tile = (b >> 7) * NTx + (n >> 7);
        float4 s = sum_tile4(P, s_lut, s_cnt, tile, b & 127, n & 127);
        float4 bv = *reinterpret_cast<const float4*>(bias + n);
        *reinterpret_cast<float4*>(out + (size_t)b * C_ + n) =
            make_float4(s.x + bv.x, s.y + bv.y, s.z + bv.z, s.w + bv.w);
    }
}

__device__ __noinline__ void phase_proto(const float* __restrict__ x,
                                         const float* __restrict__ protos,
                                         float* __restrict__ out) {
    const int D4 = D_ / 4;
    for (int t = blockIdx.x * 256 + threadIdx.x; t < C_ * D4; t += GRID_G * 256) {
        int c = t / D4, d4 = t % D4;
        float s = g_scale[c];
        float4 v[N_];
#pragma unroll
        for (int n = 0; n < N_; n++) {
            float4 p = *reinterpret_cast<const float4*>(protos + ((size_t)c * N_ + n) * D_ + d4 * 4);
            v[n] = make_float4(p.x * s, p.y * s, p.z * s, p.w * s);
        }
        int e = g_off[c + 1];
        for (int j = g_off[c]; j < e; j++) {
            int i = g_idx[j];
            float w = g_w[j];
#pragma unroll
            for (int n = 0; n < N_; n++) {
                float4 xv = *reinterpret_cast<const float4*>(x + ((size_t)i * N_ + n) * D_ + d4 * 4);
                v[n].x += w * xv.x; v[n].y += w * xv.y;
                v[n].z += w * xv.z; v[n].w += w * xv.w;
            }
        }
        float4 nrm4 = make_float4(0.f, 0.f, 0.f, 0.f);
#pragma unroll
        for (int n = 0; n < N_; n++) {
            nrm4.x += v[n].x * v[n].x; nrm4.y += v[n].y * v[n].y;
            nrm4.z += v[n].z * v[n].z; nrm4.w += v[n].w * v[n].w;
        }
        float4 inv = make_float4(1.f / fmaxf(sqrtf(nrm4.x), EPS_), 1.f / fmaxf(sqrtf(nrm4.y), EPS_),
                                 1.f / fmaxf(sqrtf(nrm4.z), EPS_), 1.f / fmaxf(sqrtf(nrm4.w), EPS_));
#pragma unroll
        for (int n = 0; n < N_; n++) {
            float4 o = make_float4(v[n].x * inv.x, v[n].y * inv.y, v[n].z * inv.z, v[n].w * inv.w);
            *reinterpret_cast<float4*>(out + ((size_t)c * N_ + n) * D_ + d4 * 4) = o;
        }
    }
}

// ==================== megakernel ====================
#define SMEM_TOTAL_GEMM 75776
__global__ void __launch_bounds__(256, 2)
mega_kernel(const float* __restrict__ x, const int* __restrict__ tgt,
            const float* __restrict__ prot, const float* __restrict__ adj,
            const float* __restrict__ W1, const float* __restrict__ W2,
            const float* __restrict__ Wg, const float* __restrict__ bg,
            const float* __restrict__ Wc, const float* __restrict__ bc,
            float* __restrict__ pred_out, float* __restrict__ proto_out,
            __nv_bfloat16* ax_hi, __nv_bfloat16* ax_lo,
            __nv_bfloat16* ah_hi, __nv_bfloat16* ah_lo,
            __nv_bfloat16* nd_hi, __nv_bfloat16* nd_lo,
            __nv_bfloat16* gg_hi, __nv_bfloat16* gg_lo,
            float* part) {
    extern __shared__ __align__(16) uint8_t smem[];

    // P0: adjmix (blocks 1..295) || class metadata (block 0)
    if (blockIdx.x == 0) phase_meta(tgt, smem);
    else phase_adjmix(x, adj, ax_hi, ax_lo);
    gbar(0);
    // P1: GEMM1  [1280,2048]@W1 -> partials
    phase_gemm(ax_hi, ax_lo, W1, part, H_, D_, 8, 80, 64, smem);
    gbar(1);
    // P2: reduce1 (relu+adjmix+convert)
    phase_r1(part, adj, ah_hi, ah_lo, smem);
    gbar(2);
    // P3: GEMM2
    phase_gemm(ah_hi, ah_lo, W2, part, D_, H_, 16, 160, 32, smem);
    gbar(3);
    // P4: reduce2
    phase_rconv(part, B_ * N_, D_, nullptr, nd_hi, nd_lo, 16, 160, 32, 5120, smem);
    gbar(4);
    // P5: fc_g
    phase_gemm(nd_hi, nd_lo, Wg, part, D_, N_ * D_, 16, 32, 320, smem);
    gbar(5);
    // P6: reduce3 (+bg)
    phase_rconv(part, B_, D_, bg, gg_hi, gg_lo, 16, 32, 320, 10240, smem);
    gbar(6);
    // P7: fc_cls
    phase_gemm(gg_hi, gg_lo, Wc, part, C_, D_, 8, 16, 64, smem);
    gbar(7);
    // P8: reduce4 (+bc, strip pad) + proto update (independent)
    phase_r4(part, bc, pred_out, smem);
    phase_proto(x, prot, proto_out);
}

// ==================== launch ====================
extern "C" void kernel_launch(void* const* d_in, const int* in_sizes, int n_in,
                              void* d_out, int out_size) {
    const float* x    = (const float*)d_in[0];
    const int*   tgt  = (const int*)d_in[1];
    const float* prot = (const float*)d_in[2];
    const float* adj  = (const float*)d_in[3];
    const float* W1   = (const float*)d_in[4];
    const float* W2   = (const float*)d_in[5];
    const float* Wg   = (const float*)d_in[6];
    const float* bg   = (const float*)d_in[7];
    const float* Wc   = (const float*)d_in[8];
    const float* bc   = (const float*)d_in[9];

    float* pred_out  = (float*)d_out;
    float* proto_out = (float*)d_out + (size_t)B_ * C_;

    __nv_bfloat16 *ax_hi, *ax_lo, *ah_hi, *ah_lo, *nd_hi, *nd_lo, *gg_hi, *gg_lo;
    float* part;
    cudaGetSymbolAddress((void**)&ax_hi, g_ax_hi);   cudaGetSymbolAddress((void**)&ax_lo, g_ax_lo);
    cudaGetSymbolAddress((void**)&ah_hi, g_ah_hi);   cudaGetSymbolAddress((void**)&ah_lo, g_ah_lo);
    cudaGetSymbolAddress((void**)&nd_hi, g_nd_hi);   cudaGetSymbolAddress((void**)&nd_lo, g_nd_lo);
    cudaGetSymbolAddress((void**)&gg_hi, g_g_hi);    cudaGetSymbolAddress((void**)&gg_lo, g_g_lo);
    cudaGetSymbolAddress((void**)&part, g_part);

    cudaFuncSetAttribute(mega_kernel, cudaFuncAttributeMaxDynamicSharedMemorySize,
                         SMEM_TOTAL_GEMM);

    mega_kernel<<<GRID_G, 256, SMEM_TOTAL_GEMM>>>(
        x, tgt, prot, adj, W1, W2, Wg, bg, Wc, bc, pred_out, proto_out,
        ax_hi, ax_lo, ah_hi, ah_lo, nd_hi, nd_lo, gg_hi, gg_lo, part);
}